// round 9
// baseline (speedup 1.0000x reference)
#include <cuda_runtime.h>
#include <cstdint>

// out[n,o,s] = sum_k din[j,k] * W[o,k] + b[o],  j = n*6+s, K=96 (k = 3c+tap)
// mma.sync.m16n8k8.row.col.f32.tf32.tf32.f32 (plain PTX, compute_103-safe).
//
// A layout, value (row r, kt, t) with t&3 = c&3, khigh = t>>2, rho = kt&3:
//   word = (r>>4)*1536 + kt*128 + (((r&7) ^ ((r>>1)&1))<<4)
//        + (((c&3) ^ ((r>>1)&3))<<2) + ((((r>>3)&1)<<1 | khigh) ^ rho)
// x-taps: kt=c>>2, khigh=par (par pairs adjacent -> STS.64). d-tap: kt=8+(c>>3), khigh=(c>>2)&1.
// B stays in global WF_g (L1-resident), bias via LDG.

#define ROWS 192
#define THREADS 384
#define SMEM_TOTAL 73728
#define EPI_STRIDE 200

__device__ __align__(16) float WF_g[3072];

__global__ void prep_WF(const float* __restrict__ W) {
    int t = blockIdx.x * blockDim.x + threadIdx.x;
    if (t < 3072) {
        int o = t / 96, k = t - 96 * o;
        int c = k / 3, tap = k - 3 * c;
        int kt, tc;
        if (tap < 2) { kt = c >> 2;       tc = (c & 3) + 4 * tap; }
        else         { kt = 8 + (c >> 3); tc = c & 7; }
        uint32_t v;
        asm("cvt.rna.tf32.f32 %0, %1;" : "=r"(v) : "f"(W[t]));
        int word = (kt * 4 + (o >> 3)) * 64 + ((o & 7) * 4 + (tc & 3)) * 2 + (tc >> 2);
        WF_g[word] = __uint_as_float(v);
    }
}

static __device__ __forceinline__ uint32_t smem_u32(const void* p) {
    uint32_t a;
    asm("{ .reg .u64 t; cvta.to.shared.u64 t, %1; cvt.u32.u64 %0, t; }" : "=r"(a) : "l"(p));
    return a;
}
static __device__ __forceinline__ uint32_t cvt_tf32(float v) {
    uint32_t t;
    asm("cvt.rna.tf32.f32 %0, %1;" : "=r"(t) : "f"(v));
    return t;
}
static __device__ __forceinline__ void sts_v2(int addr, uint32_t lo, uint32_t hi) {
    asm volatile("st.shared.v2.b32 [%0], {%1, %2};" :: "r"(addr), "r"(lo), "r"(hi));
}
static __device__ __forceinline__ void sts_b32(int addr, uint32_t v) {
    asm volatile("st.shared.b32 [%0], %1;" :: "r"(addr), "r"(v));
}
static __device__ __forceinline__ void mma4(float* a, uint32_t a0, uint32_t a1,
                                            uint32_t a2, uint32_t a3, uint2 bv) {
    asm volatile(
        "mma.sync.aligned.m16n8k8.row.col.f32.tf32.tf32.f32 "
        "{%0,%1,%2,%3}, {%4,%5,%6,%7}, {%8,%9}, {%0,%1,%2,%3};"
        : "+f"(a[0]), "+f"(a[1]), "+f"(a[2]), "+f"(a[3])
        : "r"(a0), "r"(a1), "r"(a2), "r"(a3), "r"(bv.x), "r"(bv.y));
}

// x pair-base word (par pair occupies {word, word+1}; order swapped when rho&1)
static __device__ __forceinline__ int xword(int r, int c) {
    int kt = c >> 2, rho = kt & 3;
    return (r >> 4) * 1536 + kt * 128 + (((r & 7) ^ ((r >> 1) & 1)) << 4)
         + (((c & 3) ^ ((r >> 1) & 3)) << 2) + ((((r >> 3) & 1) << 1) ^ (rho & 2));
}
static __device__ __forceinline__ int dword_(int r, int c) {
    int kt = 8 + (c >> 3), rho = kt & 3, khigh = (c >> 2) & 1;
    return (r >> 4) * 1536 + kt * 128 + (((r & 7) ^ ((r >> 1) & 1)) << 4)
         + (((c & 3) ^ ((r >> 1) & 3)) << 2) + (((((r >> 3) & 1) << 1) | khigh) ^ rho);
}

template<bool FULL>
static __device__ __forceinline__ void stage_all(
    const float4* x4, const float4* d4, int sbA, int tid, int n0, int nsamp)
{
    // ---- x: thread owns (i0=tid/96, rem); 4 double-steps of +8 samples ----
    {
        const int i0  = tid / 96;
        const int rem = tid - 96 * i0;
        const int c   = rem / 3, qq = rem - 3 * c;
        const bool sw = (c >> 2) & 1;              // rho&1
        const int rA  = 6 * i0 + 2 * qq;
        int aA0 = sbA + 4 * xword(rA,      c);
        int aB0 = sbA + 4 * xword(rA + 1,  c);
        int aA1 = sbA + 4 * xword(rA + 24, c);
        int aB1 = sbA + 4 * xword(rA + 25, c);
        int g = (n0 + i0) * 96 + rem;
        int n = n0 + i0;
        #pragma unroll
        for (int ds = 0; ds < 4; ds++) {
            if (FULL || n < nsamp) {
                float4 v = x4[g];
                uint32_t e0 = cvt_tf32(v.x), e1 = cvt_tf32(v.y);
                uint32_t e2 = cvt_tf32(v.z), e3 = cvt_tf32(v.w);
                if (sw) { sts_v2(aA0, e1, e0); sts_v2(aB0, e3, e2); }
                else    { sts_v2(aA0, e0, e1); sts_v2(aB0, e2, e3); }
            }
            if (FULL || n + 4 < nsamp) {
                float4 v = x4[g + 384];
                uint32_t e0 = cvt_tf32(v.x), e1 = cvt_tf32(v.y);
                uint32_t e2 = cvt_tf32(v.z), e3 = cvt_tf32(v.w);
                if (sw) { sts_v2(aA1, e1, e0); sts_v2(aB1, e3, e2); }
                else    { sts_v2(aA1, e0, e1); sts_v2(aB1, e2, e3); }
            }
            g += 768; n += 8;
            aA0 += 18432; aB0 += 18432; aA1 += 18432; aB1 += 18432;
        }
    }
    // ---- d: thread owns (i0=tid/48, rem); 4 steps of +8 samples (h invariant) ----
    {
        const int i0  = tid / 48;
        const int rem = tid - 48 * i0;
        int addr[4];
        #pragma unroll
        for (int e = 0; e < 4; e++) {
            int f = 4 * rem + e;
            int c = f / 6, s = f - 6 * c;
            addr[e] = sbA + 4 * dword_(6 * i0 + s, c);
        }
        int g = (n0 + i0) * 48 + rem;
        int n = n0 + i0;
        #pragma unroll
        for (int st = 0; st < 4; st++) {
            if (FULL || n < nsamp) {
                float4 v = d4[g];
                sts_b32(addr[0], cvt_tf32(v.x)); sts_b32(addr[1], cvt_tf32(v.y));
                sts_b32(addr[2], cvt_tf32(v.z)); sts_b32(addr[3], cvt_tf32(v.w));
            }
            g += 384; n += 8;
            #pragma unroll
            for (int e = 0; e < 4; e++) addr[e] += 18432;
        }
    }
}

#define SEL(i, R) (((((i) & 1) << 1) | ((i) >> 1)) ^ (R))

__global__ void __launch_bounds__(THREADS, 3)
dijet_mma(const float* __restrict__ x, const float* __restrict__ dd,
          const float* __restrict__ bvec, float* __restrict__ out, int nsamp)
{
    extern __shared__ char smem[];
    const uint32_t sb = smem_u32(smem);
    const int tid = threadIdx.x;
    const int j0  = blockIdx.x * ROWS;
    const int n0  = j0 / 6;
    const bool full = (nsamp - n0) >= 32;

    if (full) stage_all<true >((const float4*)x, (const float4*)dd, (int)sb, tid, n0, nsamp);
    else      stage_all<false>((const float4*)x, (const float4*)dd, (int)sb, tid, n0, nsamp);
    __syncthreads();

    const int wid = tid >> 5, lane = tid & 31;
    const int g8 = lane >> 2, t4 = lane & 3;

    float acc0[4][4], acc1[4][4];

    if (wid < 6) {
        const float2* b2 = (const float2*)bvec;
        #pragma unroll
        for (int nt = 0; nt < 4; nt++) {
            float2 bb = b2[nt * 4 + t4];
            acc0[nt][0] = bb.x; acc0[nt][1] = bb.y; acc0[nt][2] = bb.x; acc0[nt][3] = bb.y;
            acc1[nt][0] = bb.x; acc1[nt][1] = bb.y; acc1[nt][2] = bb.x; acc1[nt][3] = bb.y;
        }
        const int aoff = ((g8 ^ ((g8 >> 1) & 1)) << 6) + ((t4 ^ ((g8 >> 1) & 3)) << 4);
        const char* a0base = smem + (2 * wid)     * 6144 + aoff;
        const char* a1base = smem + (2 * wid + 1) * 6144 + aoff;
        const uint2* bfr = (const uint2*)WF_g + lane;

#define KSTEP(KT, RHO) { \
        uint4 av0 = *(const uint4*)(a0base + (KT) * 512); \
        uint4 av1 = *(const uint4*)(a1base + (KT) * 512); \
        uint32_t p0[4] = {av0.x, av0.y, av0.z, av0.w}; \
        uint32_t p1[4] = {av1.x, av1.y, av1.z, av1.w}; \
        _Pragma("unroll") \
        for (int nt = 0; nt < 4; nt++) { \
            uint2 bv = bfr[((KT) * 4 + nt) * 32]; \
            mma4(acc0[nt], p0[SEL(0,RHO)], p0[SEL(1,RHO)], p0[SEL(2,RHO)], p0[SEL(3,RHO)], bv); \
            mma4(acc1[nt], p1[SEL(0,RHO)], p1[SEL(1,RHO)], p1[SEL(2,RHO)], p1[SEL(3,RHO)], bv); \
        } }

        KSTEP(0, 0) KSTEP(1, 1) KSTEP(2, 2) KSTEP(3, 3)
        KSTEP(4, 0) KSTEP(5, 1) KSTEP(6, 2) KSTEP(7, 3)
        KSTEP(8, 0) KSTEP(9, 1) KSTEP(10, 2) KSTEP(11, 3)
#undef KSTEP
    }

    // ---- epilogue: scatter to smem (stride-200), then coalesced copy-out ----
    __syncthreads();
    if (wid < 6) {
        float* ep = (float*)smem;
        #pragma unroll
        for (int mt = 0; mt < 2; mt++) {
            const float (*ac)[4] = mt ? acc1 : acc0;
            #pragma unroll
            for (int h = 0; h < 2; h++) {
                int r = (2 * wid + mt) * 16 + g8 + 8 * h;
                int i = r / 6, s = r - 6 * i;
                int base = i * EPI_STRIDE + s;
                #pragma unroll
                for (int nt = 0; nt < 4; nt++) {
                    int o = nt * 8 + 2 * t4;
                    ep[base + o * 6]       = ac[nt][2 * h];
                    ep[base + (o + 1) * 6] = ac[nt][2 * h + 1];
                }
            }
        }
    }
    __syncthreads();
    {
        const int i0 = tid / 48;
        const int m0 = (tid - 48 * i0) * 4;
        const float* ep = (const float*)smem + i0 * EPI_STRIDE + m0;
        float* ob = out + (size_t)n0 * 192 + tid * 4;
        if (full) {
            #pragma unroll
            for (int it = 0; it < 4; it++) {
                float4 v = *(const float4*)(ep + it * (8 * EPI_STRIDE));
                *(float4*)(ob + it * 1536) = v;
            }
        } else {
            int limit = (nsamp - n0) * 192;
            #pragma unroll
            for (int it = 0; it < 4; it++) {
                if (tid * 4 + it * 1536 < limit) {
                    float4 v = *(const float4*)(ep + it * (8 * EPI_STRIDE));
                    *(float4*)(ob + it * 1536) = v;
                }
            }
        }
    }
}

extern "C" void kernel_launch(void* const* d_in, const int* in_sizes, int n_in,
                              void* d_out, int out_size) {
    const float* x = (const float*)d_in[0];
    const float* d = (const float*)d_in[1];
    const float* W = (const float*)d_in[2];
    const float* b = (const float*)d_in[3];
    float* out = (float*)d_out;

    int nsamp = in_sizes[0] / 384;

    cudaFuncSetAttribute(dijet_mma, cudaFuncAttributeMaxDynamicSharedMemorySize, SMEM_TOTAL);
    prep_WF<<<24, 128>>>(W);
    int nblk = (nsamp * 6 + ROWS - 1) / ROWS;
    dijet_mma<<<nblk, THREADS, SMEM_TOTAL>>>(x, d, b, out, nsamp);
}

// round 10
// speedup vs baseline: 1.2418x; 1.2418x over previous
#include <cuda_runtime.h>
#include <cstdint>

// out[n,o,s] = sum_k din[j,k] * W[o,k] + b[o],  j = n*6+s, K=96 (k = 3c+tap)
// mma.sync.m16n8k8.row.col.f32.tf32.tf32.f32 (plain PTX, compute_103-safe).
//
// A layout, value (row r, kt, t) with t&3 = c&3, khigh = t>>2, rho = kt&3:
//   word = (r>>4)*1536 + kt*128 + (((r&7) ^ ((r>>1)&1))<<4)
//        + (((c&3) ^ ((r>>1)&3))<<2) + ((((r>>3)&1)<<1 | khigh) ^ rho)
// x-taps: kt=c>>2, khigh=par (parity pairs adjacent -> STS.64, SEL-swapped when rho&1).
// d-tap:  kt=8+(c>>3), khigh=(c>>2)&1.
// B pre-packed fragment-order in WF_g, block-copied to smem (R8 scheme: LDS.64 in loop).

#define ROWS 192
#define THREADS 384
#define A_BYTES 73728
#define B_OFF A_BYTES
#define B_BYTES 12288
#define SMEM_TOTAL (A_BYTES + B_BYTES)     // 86016 -> 2 CTAs/SM
#define EPI_STRIDE 200

__device__ __align__(16) float WF_g[3072];

__global__ void prep_WF(const float* __restrict__ W) {
    int t = blockIdx.x * blockDim.x + threadIdx.x;
    if (t < 3072) {
        int o = t / 96, k = t - 96 * o;
        int c = k / 3, tap = k - 3 * c;
        int kt, tc;
        if (tap < 2) { kt = c >> 2;       tc = (c & 3) + 4 * tap; }
        else         { kt = 8 + (c >> 3); tc = c & 7; }
        uint32_t v;
        asm("cvt.rna.tf32.f32 %0, %1;" : "=r"(v) : "f"(W[t]));
        int word = (kt * 4 + (o >> 3)) * 64 + ((o & 7) * 4 + (tc & 3)) * 2 + (tc >> 2);
        WF_g[word] = __uint_as_float(v);
    }
}

static __device__ __forceinline__ uint32_t smem_u32(const void* p) {
    uint32_t a;
    asm("{ .reg .u64 t; cvta.to.shared.u64 t, %1; cvt.u32.u64 %0, t; }" : "=r"(a) : "l"(p));
    return a;
}
static __device__ __forceinline__ uint32_t cvt_tf32(float v) {
    uint32_t t;
    asm("cvt.rna.tf32.f32 %0, %1;" : "=r"(t) : "f"(v));
    return t;
}
static __device__ __forceinline__ void sts_v2(int addr, uint32_t lo, uint32_t hi) {
    asm volatile("st.shared.v2.b32 [%0], {%1, %2};" :: "r"(addr), "r"(lo), "r"(hi));
}
static __device__ __forceinline__ void sts_b32(int addr, uint32_t v) {
    asm volatile("st.shared.b32 [%0], %1;" :: "r"(addr), "r"(v));
}
static __device__ __forceinline__ void mma4(float* a, uint32_t a0, uint32_t a1,
                                            uint32_t a2, uint32_t a3, uint2 bv) {
    asm volatile(
        "mma.sync.aligned.m16n8k8.row.col.f32.tf32.tf32.f32 "
        "{%0,%1,%2,%3}, {%4,%5,%6,%7}, {%8,%9}, {%0,%1,%2,%3};"
        : "+f"(a[0]), "+f"(a[1]), "+f"(a[2]), "+f"(a[3])
        : "r"(a0), "r"(a1), "r"(a2), "r"(a3), "r"(bv.x), "r"(bv.y));
}

// x pair-base word (parity pair occupies {word, word+1}; order swapped when rho&1)
static __device__ __forceinline__ int xword(int r, int c) {
    int kt = c >> 2, rho = kt & 3;
    return (r >> 4) * 1536 + kt * 128 + (((r & 7) ^ ((r >> 1) & 1)) << 4)
         + (((c & 3) ^ ((r >> 1) & 3)) << 2) + ((((r >> 3) & 1) << 1) ^ (rho & 2));
}
static __device__ __forceinline__ int dword_(int r, int c) {
    int kt = 8 + (c >> 3), rho = kt & 3, khigh = (c >> 2) & 1;
    return (r >> 4) * 1536 + kt * 128 + (((r & 7) ^ ((r >> 1) & 1)) << 4)
         + (((c & 3) ^ ((r >> 1) & 3)) << 2) + (((((r >> 3) & 1) << 1) | khigh) ^ rho);
}

template<bool FULL>
static __device__ __forceinline__ void stage_all(
    const float4* x4, const float4* d4, int sbA, int tid, int n0, int nsamp)
{
    // ---- x: thread owns (i0=tid/96, rem); 4 double-steps of +8 samples ----
    {
        const int i0  = tid / 96;
        const int rem = tid - 96 * i0;
        const int c   = rem / 3, qq = rem - 3 * c;
        const bool sw = (c >> 2) & 1;              // rho&1
        const int rA  = 6 * i0 + 2 * qq;
        int aA0 = sbA + 4 * xword(rA,      c);
        int aB0 = sbA + 4 * xword(rA + 1,  c);
        int aA1 = sbA + 4 * xword(rA + 24, c);
        int aB1 = sbA + 4 * xword(rA + 25, c);
        int g = (n0 + i0) * 96 + rem;
        int n = n0 + i0;
        #pragma unroll
        for (int ds = 0; ds < 4; ds++) {
            if (FULL || n < nsamp) {
                float4 v = x4[g];
                uint32_t e0 = cvt_tf32(v.x), e1 = cvt_tf32(v.y);
                uint32_t e2 = cvt_tf32(v.z), e3 = cvt_tf32(v.w);
                if (sw) { sts_v2(aA0, e1, e0); sts_v2(aB0, e3, e2); }
                else    { sts_v2(aA0, e0, e1); sts_v2(aB0, e2, e3); }
            }
            if (FULL || n + 4 < nsamp) {
                float4 v = x4[g + 384];
                uint32_t e0 = cvt_tf32(v.x), e1 = cvt_tf32(v.y);
                uint32_t e2 = cvt_tf32(v.z), e3 = cvt_tf32(v.w);
                if (sw) { sts_v2(aA1, e1, e0); sts_v2(aB1, e3, e2); }
                else    { sts_v2(aA1, e0, e1); sts_v2(aB1, e2, e3); }
            }
            g += 768; n += 8;
            aA0 += 18432; aB0 += 18432; aA1 += 18432; aB1 += 18432;
        }
    }
    // ---- d: thread owns (i0=tid/48, rem); 4 steps of +8 samples (h invariant) ----
    {
        const int i0  = tid / 48;
        const int rem = tid - 48 * i0;
        int addr[4];
        #pragma unroll
        for (int e = 0; e < 4; e++) {
            int f = 4 * rem + e;
            int c = f / 6, s = f - 6 * c;
            addr[e] = sbA + 4 * dword_(6 * i0 + s, c);
        }
        int g = (n0 + i0) * 48 + rem;
        int n = n0 + i0;
        #pragma unroll
        for (int st = 0; st < 4; st++) {
            if (FULL || n < nsamp) {
                float4 v = d4[g];
                sts_b32(addr[0], cvt_tf32(v.x)); sts_b32(addr[1], cvt_tf32(v.y));
                sts_b32(addr[2], cvt_tf32(v.z)); sts_b32(addr[3], cvt_tf32(v.w));
            }
            g += 384; n += 8;
            #pragma unroll
            for (int e = 0; e < 4; e++) addr[e] += 18432;
        }
    }
}

#define SEL(i, R) (((((i) & 1) << 1) | ((i) >> 1)) ^ (R))

__global__ void __launch_bounds__(THREADS, 2)
dijet_mma(const float* __restrict__ x, const float* __restrict__ dd,
          const float* __restrict__ bvec, float* __restrict__ out, int nsamp)
{
    extern __shared__ char smem[];
    const uint32_t sb = smem_u32(smem);
    const int tid = threadIdx.x;
    const int j0  = blockIdx.x * ROWS;
    const int n0  = j0 / 6;
    const bool full = (nsamp - n0) >= 32;

    // ---- stage B (pre-packed image) into smem ----
    {
        const float4* wf4 = (const float4*)WF_g;
        float4* b4 = (float4*)(smem + B_OFF);
        #pragma unroll
        for (int t = tid; t < B_BYTES / 16; t += THREADS) b4[t] = wf4[t];
    }

    if (full) stage_all<true >((const float4*)x, (const float4*)dd, (int)sb, tid, n0, nsamp);
    else      stage_all<false>((const float4*)x, (const float4*)dd, (int)sb, tid, n0, nsamp);
    __syncthreads();

    const int wid = tid >> 5, lane = tid & 31;
    const int g8 = lane >> 2, t4 = lane & 3;

    float acc0[4][4], acc1[4][4];

    if (wid < 6) {
        const float2* b2 = (const float2*)bvec;
        #pragma unroll
        for (int nt = 0; nt < 4; nt++) {
            float2 bb = b2[nt * 4 + t4];
            acc0[nt][0] = bb.x; acc0[nt][1] = bb.y; acc0[nt][2] = bb.x; acc0[nt][3] = bb.y;
            acc1[nt][0] = bb.x; acc1[nt][1] = bb.y; acc1[nt][2] = bb.x; acc1[nt][3] = bb.y;
        }
        const int aoff = ((g8 ^ ((g8 >> 1) & 1)) << 6) + ((t4 ^ ((g8 >> 1) & 3)) << 4);
        const char* a0base = smem + (2 * wid)     * 6144 + aoff;
        const char* a1base = smem + (2 * wid + 1) * 6144 + aoff;
        const char* bbase  = smem + B_OFF + lane * 8;

#define KSTEP(KT, RHO) { \
        uint4 av0 = *(const uint4*)(a0base + (KT) * 512); \
        uint4 av1 = *(const uint4*)(a1base + (KT) * 512); \
        uint32_t p0[4] = {av0.x, av0.y, av0.z, av0.w}; \
        uint32_t p1[4] = {av1.x, av1.y, av1.z, av1.w}; \
        _Pragma("unroll") \
        for (int nt = 0; nt < 4; nt++) { \
            uint2 bv = *(const uint2*)(bbase + ((KT) * 4 + nt) * 256); \
            mma4(acc0[nt], p0[SEL(0,RHO)], p0[SEL(1,RHO)], p0[SEL(2,RHO)], p0[SEL(3,RHO)], bv); \
            mma4(acc1[nt], p1[SEL(0,RHO)], p1[SEL(1,RHO)], p1[SEL(2,RHO)], p1[SEL(3,RHO)], bv); \
        } }

        KSTEP(0, 0) KSTEP(1, 1) KSTEP(2, 2) KSTEP(3, 3)
        KSTEP(4, 0) KSTEP(5, 1) KSTEP(6, 2) KSTEP(7, 3)
        KSTEP(8, 0) KSTEP(9, 1) KSTEP(10, 2) KSTEP(11, 3)
#undef KSTEP
    }

    // ---- epilogue: scatter to smem (stride-200), then coalesced copy-out ----
    __syncthreads();
    if (wid < 6) {
        float* ep = (float*)smem;
        #pragma unroll
        for (int mt = 0; mt < 2; mt++) {
            const float (*ac)[4] = mt ? acc1 : acc0;
            #pragma unroll
            for (int h = 0; h < 2; h++) {
                int r = (2 * wid + mt) * 16 + g8 + 8 * h;
                int i = r / 6, s = r - 6 * i;
                int base = i * EPI_STRIDE + s;
                #pragma unroll
                for (int nt = 0; nt < 4; nt++) {
                    int o = nt * 8 + 2 * t4;
                    ep[base + o * 6]       = ac[nt][2 * h];
                    ep[base + (o + 1) * 6] = ac[nt][2 * h + 1];
                }
            }
        }
    }
    __syncthreads();
    {
        const int i0 = tid / 48;
        const int m0 = (tid - 48 * i0) * 4;
        const float* ep = (const float*)smem + i0 * EPI_STRIDE + m0;
        float* ob = out + (size_t)n0 * 192 + tid * 4;
        if (full) {
            #pragma unroll
            for (int it = 0; it < 4; it++) {
                float4 v = *(const float4*)(ep + it * (8 * EPI_STRIDE));
                *(float4*)(ob + it * 1536) = v;
            }
        } else {
            int limit = (nsamp - n0) * 192;
            #pragma unroll
            for (int it = 0; it < 4; it++) {
                if (tid * 4 + it * 1536 < limit) {
                    float4 v = *(const float4*)(ep + it * (8 * EPI_STRIDE));
                    *(float4*)(ob + it * 1536) = v;
                }
            }
        }
    }
}

extern "C" void kernel_launch(void* const* d_in, const int* in_sizes, int n_in,
                              void* d_out, int out_size) {
    const float* x = (const float*)d_in[0];
    const float* d = (const float*)d_in[1];
    const float* W = (const float*)d_in[2];
    const float* b = (const float*)d_in[3];
    float* out = (float*)d_out;

    int nsamp = in_sizes[0] / 384;

    cudaFuncSetAttribute(dijet_mma, cudaFuncAttributeMaxDynamicSharedMemorySize, SMEM_TOTAL);
    prep_WF<<<24, 128>>>(W);
    int nblk = (nsamp * 6 + ROWS - 1) / ROWS;
    dijet_mma<<<nblk, THREADS, SMEM_TOTAL>>>(x, d, b, out, nsamp);
}